// round 4
// baseline (speedup 1.0000x reference)
#include <cuda_runtime.h>
#include <cuda_bf16.h>
#include <cstdint>

#define N_NODES 100000
#define N_EDGES 1600000
#define D_IN    32
#define D_OUT   64
#define CAP     64          // padded bucket capacity per node (max deg ~45 for this dist)

// ---------------- scratch (static __device__ allocations only) ----------------
__device__ float g_xbuf0[N_NODES * D_IN];
__device__ float g_xbuf1[N_NODES * D_IN];
__device__ int   g_cnt[N_NODES];
__device__ int2  g_csr[(size_t)N_NODES * CAP];   // {col, val bits}, padded buckets

// ---------------- CSR build: single pass into padded buckets ----------------
__global__ void k_build(const int* __restrict__ row,
                        const int* __restrict__ col,
                        const float* __restrict__ val) {
    int e = blockIdx.x * blockDim.x + threadIdx.x;
    if (e < N_EDGES) {
        int r = row[e];
        int c = col[e];
        float v = val[e];
        int p = atomicAdd(&g_cnt[r], 1);
        if (p < CAP)
            g_csr[(size_t)r * CAP + p] = make_int2(c, __float_as_int(v));
    }
}

// ---------------- SpMM: warp per node (grid-stride), float4 features --------
// lane = grp*8 + sub ; grp in [0,4) picks edge within quad, sub picks float4 chunk
template <bool FUSE>
__global__ __launch_bounds__(256) void k_spmm(const float* __restrict__ xin,
                                              float* __restrict__ xout,
                                              const float* __restrict__ W,
                                              const float* __restrict__ b) {
    __shared__ float Ws[D_IN * D_OUT];   // 8 KB
    __shared__ float bs[D_OUT];
    if (FUSE) {
        for (int i = threadIdx.x; i < D_IN * D_OUT; i += blockDim.x) Ws[i] = W[i];
        if (threadIdx.x < D_OUT) bs[threadIdx.x] = b[threadIdx.x];
        __syncthreads();
    }

    int lane = threadIdx.x & 31;
    int grp  = lane >> 3;     // 0..3 : which edge of the quad
    int sub  = lane & 7;      // 0..7 : which float4 of the 32 features
    int warp0   = (blockIdx.x * blockDim.x + threadIdx.x) >> 5;
    int nwarps  = (gridDim.x * blockDim.x) >> 5;

    for (int node = warp0; node < N_NODES; node += nwarps) {
        int cnt = __ldg(&g_cnt[node]);
        if (cnt > CAP) cnt = CAP;
        const int2* csr = g_csr + (size_t)node * CAP;

        float4 acc = make_float4(0.f, 0.f, 0.f, 0.f);
        int e = 0;
        // 16 edges per iter: 4 independent 128B gathers in flight per lane-quad
        for (; e + 16 <= cnt; e += 16) {
            int2 cv0 = __ldg(&csr[e      + grp]);
            int2 cv1 = __ldg(&csr[e + 4  + grp]);
            int2 cv2 = __ldg(&csr[e + 8  + grp]);
            int2 cv3 = __ldg(&csr[e + 12 + grp]);
            float4 x0 = __ldg((const float4*)(xin + (size_t)cv0.x * D_IN) + sub);
            float4 x1 = __ldg((const float4*)(xin + (size_t)cv1.x * D_IN) + sub);
            float4 x2 = __ldg((const float4*)(xin + (size_t)cv2.x * D_IN) + sub);
            float4 x3 = __ldg((const float4*)(xin + (size_t)cv3.x * D_IN) + sub);
            float v0 = __int_as_float(cv0.y);
            float v1 = __int_as_float(cv1.y);
            float v2 = __int_as_float(cv2.y);
            float v3 = __int_as_float(cv3.y);
            acc.x = fmaf(v0, x0.x, acc.x); acc.y = fmaf(v0, x0.y, acc.y);
            acc.z = fmaf(v0, x0.z, acc.z); acc.w = fmaf(v0, x0.w, acc.w);
            acc.x = fmaf(v1, x1.x, acc.x); acc.y = fmaf(v1, x1.y, acc.y);
            acc.z = fmaf(v1, x1.z, acc.z); acc.w = fmaf(v1, x1.w, acc.w);
            acc.x = fmaf(v2, x2.x, acc.x); acc.y = fmaf(v2, x2.y, acc.y);
            acc.z = fmaf(v2, x2.z, acc.z); acc.w = fmaf(v2, x2.w, acc.w);
            acc.x = fmaf(v3, x3.x, acc.x); acc.y = fmaf(v3, x3.y, acc.y);
            acc.z = fmaf(v3, x3.z, acc.z); acc.w = fmaf(v3, x3.w, acc.w);
        }
        for (; e < cnt; e += 4) {
            int ee = e + grp;
            int2 cv = (ee < cnt) ? __ldg(&csr[ee]) : make_int2(0, 0);
            float4 xv = __ldg((const float4*)(xin + (size_t)cv.x * D_IN) + sub);
            float v = __int_as_float(cv.y);
            acc.x = fmaf(v, xv.x, acc.x); acc.y = fmaf(v, xv.y, acc.y);
            acc.z = fmaf(v, xv.z, acc.z); acc.w = fmaf(v, xv.w, acc.w);
        }

        // reduce the 4 edge-groups
        #pragma unroll
        for (int off = 16; off >= 8; off >>= 1) {
            acc.x += __shfl_xor_sync(0xffffffffu, acc.x, off);
            acc.y += __shfl_xor_sync(0xffffffffu, acc.y, off);
            acc.z += __shfl_xor_sync(0xffffffffu, acc.z, off);
            acc.w += __shfl_xor_sync(0xffffffffu, acc.w, off);
        }

        if (!FUSE) {
            if (grp == 0)
                ((float4*)(xout + (size_t)node * D_IN))[sub] = acc;
        } else {
            float a0 = bs[lane];
            float a1 = bs[lane + 32];
            #pragma unroll
            for (int d = 0; d < D_IN; ++d) {
                float comp = ((d & 3) == 0) ? acc.x :
                             ((d & 3) == 1) ? acc.y :
                             ((d & 3) == 2) ? acc.z : acc.w;
                float xv = __shfl_sync(0xffffffffu, comp, d >> 2);
                a0 = fmaf(xv, Ws[d * D_OUT + lane], a0);
                a1 = fmaf(xv, Ws[d * D_OUT + lane + 32], a1);
            }
            xout[(size_t)node * D_OUT + lane]      = a0;
            xout[(size_t)node * D_OUT + lane + 32] = a1;
        }
    }
}

// ---------------- launch ----------------
extern "C" void kernel_launch(void* const* d_in, const int* in_sizes, int n_in,
                              void* d_out, int out_size) {
    const float* x   = (const float*)d_in[0];
    const int*   er  = (const int*)  d_in[1];
    const int*   ec  = (const int*)  d_in[2];
    const float* ev  = (const float*)d_in[3];
    const float* W   = (const float*)d_in[4];
    const float* b   = (const float*)d_in[5];
    float*       out = (float*)d_out;

    void* p_cnt;
    cudaGetSymbolAddress(&p_cnt, g_cnt);

    // --- CSR build: memset counts + single scatter pass ---
    cudaMemsetAsync(p_cnt, 0, N_NODES * sizeof(int));
    const int EB = 256;
    k_build<<<(N_EDGES + EB - 1) / EB, EB>>>(er, ec, ev);

    // --- 4-hop propagation (k == 4 static), final hop fuses x@W + b ---
    float* buf0;
    float* buf1;
    cudaGetSymbolAddress((void**)&buf0, g_xbuf0);
    cudaGetSymbolAddress((void**)&buf1, g_xbuf1);

    const int SB = 256;           // 8 warps per block
    const int SG = 148 * 8;       // persistent-ish: ~64 warps/SM, grid-stride

    k_spmm<false><<<SG, SB>>>(x,    buf0, nullptr, nullptr);
    k_spmm<false><<<SG, SB>>>(buf0, buf1, nullptr, nullptr);
    k_spmm<false><<<SG, SB>>>(buf1, buf0, nullptr, nullptr);
    k_spmm<true ><<<SG, SB>>>(buf0, out,  W, b);
}

// round 5
// speedup vs baseline: 1.2448x; 1.2448x over previous
#include <cuda_runtime.h>
#include <cuda_bf16.h>
#include <cstdint>

#define N_NODES 100000
#define N_EDGES 1600000
#define D_IN    32
#define D_OUT   64
#define CAP     64          // padded bucket capacity (Poisson(16) tail @64 ~ e^-40)

// ---------------- scratch (static __device__ allocations only) ----------------
__device__ float g_xbuf0[N_NODES * D_IN];
__device__ float g_xbuf1[N_NODES * D_IN];
__device__ int   g_cnt[N_NODES];
__device__ int2  g_csr[(size_t)N_NODES * CAP];   // {col, val bits}, padded buckets

// ---------------- CSR build: single pass into padded buckets ----------------
__global__ void k_build(const int* __restrict__ row,
                        const int* __restrict__ col,
                        const float* __restrict__ val) {
    int e = blockIdx.x * blockDim.x + threadIdx.x;
    if (e < N_EDGES) {
        int r = row[e];
        int c = col[e];
        float v = val[e];
        int p = atomicAdd(&g_cnt[r], 1);
        if (p < CAP)
            g_csr[(size_t)r * CAP + p] = make_int2(c, __float_as_int(v));
    }
}

__device__ __forceinline__ unsigned clampcol(int c) {
    unsigned u = (unsigned)c;
    return (u < (unsigned)N_NODES) ? u : (unsigned)(N_NODES - 1);
}

// ---------------- SpMM: one warp per node, float4 features -------------------
// lane = grp*8 + sub ; grp in [0,4) picks edge within quad, sub picks float4 chunk
// Latency trick: the first 16 csr entries + their gathers are issued UNCONDITIONALLY
// (bucket is padded, columns clamped), in parallel with the cnt load; cnt only
// predicates the FMA weights. This removes cnt from the load chain.
template <bool FUSE>
__global__ __launch_bounds__(256) void k_spmm(const float* __restrict__ xin,
                                              float* __restrict__ xout,
                                              const float* __restrict__ W,
                                              const float* __restrict__ b) {
    __shared__ float Ws[D_IN * D_OUT];   // 8 KB
    __shared__ float bs[D_OUT];
    if (FUSE) {
        for (int i = threadIdx.x; i < D_IN * D_OUT; i += blockDim.x) Ws[i] = W[i];
        if (threadIdx.x < D_OUT) bs[threadIdx.x] = b[threadIdx.x];
        __syncthreads();
    }

    int node = (blockIdx.x * blockDim.x + threadIdx.x) >> 5;
    int lane = threadIdx.x & 31;
    if (node >= N_NODES) return;
    int grp = lane >> 3;      // 0..3
    int sub = lane & 7;       // 0..7

    const int2* csr = g_csr + (size_t)node * CAP;

    // issue cnt and first-quad csr loads together
    int cnt = __ldg(&g_cnt[node]);
    int2 cv0 = __ldg(&csr[grp]);
    int2 cv1 = __ldg(&csr[4  + grp]);
    int2 cv2 = __ldg(&csr[8  + grp]);
    int2 cv3 = __ldg(&csr[12 + grp]);

    // gathers issue as soon as csr returns (no cnt dependency)
    float4 x0 = __ldg((const float4*)(xin + (size_t)clampcol(cv0.x) * D_IN) + sub);
    float4 x1 = __ldg((const float4*)(xin + (size_t)clampcol(cv1.x) * D_IN) + sub);
    float4 x2 = __ldg((const float4*)(xin + (size_t)clampcol(cv2.x) * D_IN) + sub);
    float4 x3 = __ldg((const float4*)(xin + (size_t)clampcol(cv3.x) * D_IN) + sub);

    // cnt has long since arrived; predicate the weights
    float v0 = (grp      < cnt) ? __int_as_float(cv0.y) : 0.f;
    float v1 = (grp + 4  < cnt) ? __int_as_float(cv1.y) : 0.f;
    float v2 = (grp + 8  < cnt) ? __int_as_float(cv2.y) : 0.f;
    float v3 = (grp + 12 < cnt) ? __int_as_float(cv3.y) : 0.f;

    float4 acc;
    acc.x = v0 * x0.x; acc.y = v0 * x0.y; acc.z = v0 * x0.z; acc.w = v0 * x0.w;
    acc.x = fmaf(v1, x1.x, acc.x); acc.y = fmaf(v1, x1.y, acc.y);
    acc.z = fmaf(v1, x1.z, acc.z); acc.w = fmaf(v1, x1.w, acc.w);
    acc.x = fmaf(v2, x2.x, acc.x); acc.y = fmaf(v2, x2.y, acc.y);
    acc.z = fmaf(v2, x2.z, acc.z); acc.w = fmaf(v2, x2.w, acc.w);
    acc.x = fmaf(v3, x3.x, acc.x); acc.y = fmaf(v3, x3.y, acc.y);
    acc.z = fmaf(v3, x3.z, acc.z); acc.w = fmaf(v3, x3.w, acc.w);

    // remainder (cnt > 16): ~half the nodes, usually 1 iteration
    if (cnt > CAP) cnt = CAP;
    for (int e = 16; e < cnt; e += 8) {
        int ee0 = e + grp;
        int ee1 = e + 4 + grp;
        int2 a = __ldg(&csr[ee0]);                      // always in-bounds (padded)
        int2 c = (ee1 < CAP) ? __ldg(&csr[ee1]) : make_int2(0, 0);
        float4 xa = __ldg((const float4*)(xin + (size_t)clampcol(a.x) * D_IN) + sub);
        float4 xc = __ldg((const float4*)(xin + (size_t)clampcol(c.x) * D_IN) + sub);
        float va = (ee0 < cnt) ? __int_as_float(a.y) : 0.f;
        float vc = (ee1 < cnt) ? __int_as_float(c.y) : 0.f;
        acc.x = fmaf(va, xa.x, acc.x); acc.y = fmaf(va, xa.y, acc.y);
        acc.z = fmaf(va, xa.z, acc.z); acc.w = fmaf(va, xa.w, acc.w);
        acc.x = fmaf(vc, xc.x, acc.x); acc.y = fmaf(vc, xc.y, acc.y);
        acc.z = fmaf(vc, xc.z, acc.z); acc.w = fmaf(vc, xc.w, acc.w);
    }

    // reduce the 4 edge-groups
    #pragma unroll
    for (int off = 16; off >= 8; off >>= 1) {
        acc.x += __shfl_xor_sync(0xffffffffu, acc.x, off);
        acc.y += __shfl_xor_sync(0xffffffffu, acc.y, off);
        acc.z += __shfl_xor_sync(0xffffffffu, acc.z, off);
        acc.w += __shfl_xor_sync(0xffffffffu, acc.w, off);
    }

    if (!FUSE) {
        if (grp == 0)
            ((float4*)(xout + (size_t)node * D_IN))[sub] = acc;
    } else {
        float a0 = bs[lane];
        float a1 = bs[lane + 32];
        #pragma unroll
        for (int d = 0; d < D_IN; ++d) {
            float comp = ((d & 3) == 0) ? acc.x :
                         ((d & 3) == 1) ? acc.y :
                         ((d & 3) == 2) ? acc.z : acc.w;
            float xv = __shfl_sync(0xffffffffu, comp, d >> 2);
            a0 = fmaf(xv, Ws[d * D_OUT + lane], a0);
            a1 = fmaf(xv, Ws[d * D_OUT + lane + 32], a1);
        }
        xout[(size_t)node * D_OUT + lane]      = a0;
        xout[(size_t)node * D_OUT + lane + 32] = a1;
    }
}

// ---------------- launch ----------------
extern "C" void kernel_launch(void* const* d_in, const int* in_sizes, int n_in,
                              void* d_out, int out_size) {
    const float* x   = (const float*)d_in[0];
    const int*   er  = (const int*)  d_in[1];
    const int*   ec  = (const int*)  d_in[2];
    const float* ev  = (const float*)d_in[3];
    const float* W   = (const float*)d_in[4];
    const float* b   = (const float*)d_in[5];
    float*       out = (float*)d_out;

    void* p_cnt;
    cudaGetSymbolAddress(&p_cnt, g_cnt);

    // --- build: memset counts + single scatter pass into padded buckets ---
    cudaMemsetAsync(p_cnt, 0, N_NODES * sizeof(int));
    const int EB = 256;
    k_build<<<(N_EDGES + EB - 1) / EB, EB>>>(er, ec, ev);

    // --- 4-hop propagation (k == 4 static), final hop fuses x@W + b ---
    float* buf0;
    float* buf1;
    cudaGetSymbolAddress((void**)&buf0, g_xbuf0);
    cudaGetSymbolAddress((void**)&buf1, g_xbuf1);

    const int SB = 256;                                   // 8 warps per block
    const int SG = (N_NODES + (SB / 32) - 1) / (SB / 32); // 12500 blocks

    k_spmm<false><<<SG, SB>>>(x,    buf0, nullptr, nullptr);
    k_spmm<false><<<SG, SB>>>(buf0, buf1, nullptr, nullptr);
    k_spmm<false><<<SG, SB>>>(buf1, buf0, nullptr, nullptr);
    k_spmm<true ><<<SG, SB>>>(buf0, out,  W, b);
}